// round 5
// baseline (speedup 1.0000x reference)
#include <cuda_runtime.h>

#define BB 8
#define CC 512
#define CI 256
#define NN 3136
#define EPSBN 1e-5f

// ---- scratch (static device globals; no allocations allowed) ----
__device__ __align__(16) float s_theta[BB * CI * NN];          // 25.7 MB
__device__ __align__(16) float s_phi  [BB * CI * NN];          // 25.7 MB
__device__ __align__(16) float s_g    [BB * CI * NN];          // 25.7 MB
__device__ __align__(16) float s_f    [BB * NN * NN];          // 314.7 MB
__device__ __align__(16) float s_y    [BB * CI * NN];          // 25.7 MB
__device__ __align__(16) float s_wy   [BB * CC * NN];          // 51.4 MB
__device__ float s_mean[CC];
__device__ float s_rstd[CC];

// ============================================================================
// Generic batched SGEMM: C[m][n] = sum_k A(m,k)*B(k,n) (+bias[m])
//   TA=false: A is [M x K] row-major.  TA=true: A stored [K x M] (A(m,k)=A[k*M+m])
//   TB=false: B is [K x N] row-major.  TB=true: B stored [N x K] (B(k,n)=B[n*K+k])
// Tiles: 128x128x16, 256 threads, 8x8 per thread. Requires K % 16 == 0,
// M % 4 == 0, N % 4 == 0 (true for all shapes here).
// ============================================================================
template <bool TA, bool TB, bool BIAS>
__global__ __launch_bounds__(256) void sgemm_k(
    const float* __restrict__ A, const float* __restrict__ B,
    const float* __restrict__ bias, float* __restrict__ C,
    int M, int N, int K,
    long long strideA, long long strideB, long long strideC)
{
    __shared__ float As[16][128];
    __shared__ float Bs[16][128];

    const int tid = threadIdx.x;
    const int m0 = blockIdx.y * 128;
    const int n0 = blockIdx.x * 128;
    A += (size_t)blockIdx.z * (size_t)strideA;
    B += (size_t)blockIdx.z * (size_t)strideB;
    C += (size_t)blockIdx.z * (size_t)strideC;

    const int ty = tid >> 4;        // 0..15
    const int tx = tid & 15;        // 0..15
    const int rowc = ty * 8;
    const int colc = tx * 8;

    float acc[8][8];
#pragma unroll
    for (int i = 0; i < 8; ++i)
#pragma unroll
        for (int j = 0; j < 8; ++j) acc[i][j] = 0.f;

    for (int k0 = 0; k0 < K; k0 += 16) {
        // ---- load A tile into As[k][m] ----
        if (!TA) {
            const int ar = tid >> 2;           // 0..63
            const int ac = (tid & 3) << 2;     // 0,4,8,12
#pragma unroll
            for (int r = 0; r < 2; ++r) {
                int m = m0 + ar + r * 64;
                float4 v = make_float4(0.f, 0.f, 0.f, 0.f);
                if (m < M) v = *(const float4*)(A + (size_t)m * K + k0 + ac);
                As[ac + 0][ar + r * 64] = v.x;
                As[ac + 1][ar + r * 64] = v.y;
                As[ac + 2][ar + r * 64] = v.z;
                As[ac + 3][ar + r * 64] = v.w;
            }
        } else {
            const int ak = tid >> 5;           // 0..7
            const int am = (tid & 31) << 2;    // 0..124
#pragma unroll
            for (int r = 0; r < 2; ++r) {
                int k = k0 + ak + r * 8;
                int m = m0 + am;
                float4 v = make_float4(0.f, 0.f, 0.f, 0.f);
                if (m < M) v = *(const float4*)(A + (size_t)k * M + m);
                *(float4*)&As[ak + r * 8][am] = v;
            }
        }
        // ---- load B tile into Bs[k][n] ----
        if (!TB) {
            const int bk = tid >> 5;
            const int bn = (tid & 31) << 2;
#pragma unroll
            for (int r = 0; r < 2; ++r) {
                int k = k0 + bk + r * 8;
                int n = n0 + bn;
                float4 v = make_float4(0.f, 0.f, 0.f, 0.f);
                if (n < N) v = *(const float4*)(B + (size_t)k * N + n);
                *(float4*)&Bs[bk + r * 8][bn] = v;
            }
        } else {
            const int br = tid >> 2;
            const int bc = (tid & 3) << 2;
#pragma unroll
            for (int r = 0; r < 2; ++r) {
                int n = n0 + br + r * 64;
                float4 v = make_float4(0.f, 0.f, 0.f, 0.f);
                if (n < N) v = *(const float4*)(B + (size_t)n * K + k0 + bc);
                Bs[bc + 0][br + r * 64] = v.x;
                Bs[bc + 1][br + r * 64] = v.y;
                Bs[bc + 2][br + r * 64] = v.z;
                Bs[bc + 3][br + r * 64] = v.w;
            }
        }
        __syncthreads();

#pragma unroll
        for (int k = 0; k < 16; ++k) {
            float ra[8], rb[8];
            *(float4*)&ra[0] = *(const float4*)&As[k][rowc];
            *(float4*)&ra[4] = *(const float4*)&As[k][rowc + 4];
            *(float4*)&rb[0] = *(const float4*)&Bs[k][colc];
            *(float4*)&rb[4] = *(const float4*)&Bs[k][colc + 4];
#pragma unroll
            for (int i = 0; i < 8; ++i)
#pragma unroll
                for (int j = 0; j < 8; ++j)
                    acc[i][j] = fmaf(ra[i], rb[j], acc[i][j]);
        }
        __syncthreads();
    }

    // ---- store ----
#pragma unroll
    for (int i = 0; i < 8; ++i) {
        int m = m0 + rowc + i;
        if (m >= M) continue;
        float bv = 0.f;
        if (BIAS) bv = bias[m];
        float* crow = C + (size_t)m * N;
#pragma unroll
        for (int jj = 0; jj < 2; ++jj) {
            int n = n0 + colc + jj * 4;
            if (n < N) {
                float4 v;
                v.x = acc[i][jj * 4 + 0] + bv;
                v.y = acc[i][jj * 4 + 1] + bv;
                v.z = acc[i][jj * 4 + 2] + bv;
                v.w = acc[i][jj * 4 + 3] + bv;
                *(float4*)(crow + n) = v;
            }
        }
    }
}

// ============================================================================
// Row softmax over f: one CTA (256 threads) per row of NN=3136 floats.
// Row staged in shared memory (12.5 KB): one global read + one write.
// ============================================================================
__global__ __launch_bounds__(256) void softmax_kernel(float* __restrict__ f)
{
    __shared__ float4 buf[NN / 4];       // 784 float4
    __shared__ float red[8];
    float* row = f + (size_t)blockIdx.x * NN;
    const int tid = threadIdx.x;

    float mx = -1e30f;
    for (int i = tid; i < NN / 4; i += 256) {
        float4 v = *(const float4*)(row + i * 4);
        buf[i] = v;
        mx = fmaxf(mx, fmaxf(fmaxf(v.x, v.y), fmaxf(v.z, v.w)));
    }
#pragma unroll
    for (int o = 16; o > 0; o >>= 1) mx = fmaxf(mx, __shfl_xor_sync(0xffffffffu, mx, o));
    if ((tid & 31) == 0) red[tid >> 5] = mx;
    __syncthreads();
    if (tid == 0) {
        float v = red[0];
        for (int i = 1; i < 8; ++i) v = fmaxf(v, red[i]);
        red[0] = v;
    }
    __syncthreads();
    mx = red[0];
    __syncthreads();

    float sum = 0.f;
    for (int i = tid; i < NN / 4; i += 256) {
        float4 v = buf[i];
        v.x = __expf(v.x - mx); v.y = __expf(v.y - mx);
        v.z = __expf(v.z - mx); v.w = __expf(v.w - mx);
        buf[i] = v;
        sum += v.x + v.y + v.z + v.w;
    }
#pragma unroll
    for (int o = 16; o > 0; o >>= 1) sum += __shfl_xor_sync(0xffffffffu, sum, o);
    if ((tid & 31) == 0) red[tid >> 5] = sum;
    __syncthreads();
    if (tid == 0) {
        float v = 0.f;
        for (int i = 0; i < 8; ++i) v += red[i];
        red[0] = v;
    }
    __syncthreads();
    const float inv = 1.f / red[0];

    for (int i = tid; i < NN / 4; i += 256) {
        float4 v = buf[i];
        v.x *= inv; v.y *= inv; v.z *= inv; v.w *= inv;
        *(float4*)(row + i * 4) = v;
    }
}

// ============================================================================
// BatchNorm stats: one CTA per channel, deterministic tree reduction over
// B*N = 25088 elements. Writes s_mean[c], s_rstd[c].
// ============================================================================
__global__ __launch_bounds__(256) void bnstats_kernel(const float* __restrict__ wy)
{
    const int c = blockIdx.x;
    const int tid = threadIdx.x;
    float s = 0.f, s2 = 0.f;
    for (int b = 0; b < BB; ++b) {
        const float* row = wy + ((size_t)b * CC + c) * NN;
        for (int i = tid; i < NN / 4; i += 256) {
            float4 v = *(const float4*)(row + i * 4);
            s  += v.x + v.y + v.z + v.w;
            s2 += v.x * v.x + v.y * v.y + v.z * v.z + v.w * v.w;
        }
    }
#pragma unroll
    for (int o = 16; o > 0; o >>= 1) {
        s  += __shfl_xor_sync(0xffffffffu, s, o);
        s2 += __shfl_xor_sync(0xffffffffu, s2, o);
    }
    __shared__ float rs[8], rs2[8];
    if ((tid & 31) == 0) { rs[tid >> 5] = s; rs2[tid >> 5] = s2; }
    __syncthreads();
    if (tid == 0) {
        float ts = 0.f, ts2 = 0.f;
        for (int i = 0; i < 8; ++i) { ts += rs[i]; ts2 += rs2[i]; }
        const float cnt = (float)(BB * NN);
        const float mean = ts / cnt;
        const float var = ts2 / cnt - mean * mean;
        s_mean[c] = mean;
        s_rstd[c] = rsqrtf(var + EPSBN);
    }
}

// ============================================================================
// out = BN(wy)*gamma + beta + x   (elementwise, float4)
// ============================================================================
__global__ __launch_bounds__(256) void bn_finalize_kernel(
    const float* __restrict__ wy, const float* __restrict__ x,
    const float* __restrict__ gamma, const float* __restrict__ beta,
    float* __restrict__ out)
{
    const size_t i4 = (size_t)blockIdx.x * 256 + threadIdx.x;
    const size_t total4 = (size_t)BB * CC * NN / 4;
    if (i4 >= total4) return;
    const size_t i = i4 * 4;
    const int c = (int)((i / NN) % CC);
    float4 w  = *(const float4*)(wy + i);
    float4 xv = *(const float4*)(x + i);
    const float m = s_mean[c], r = s_rstd[c];
    const float gm = gamma[c], bt = beta[c];
    float4 o;
    o.x = (w.x - m) * r * gm + bt + xv.x;
    o.y = (w.y - m) * r * gm + bt + xv.y;
    o.z = (w.z - m) * r * gm + bt + xv.z;
    o.w = (w.w - m) * r * gm + bt + xv.w;
    *(float4*)(out + i) = o;
}

// ============================================================================
// Launch
// ============================================================================
extern "C" void kernel_launch(void* const* d_in, const int* in_sizes, int n_in,
                              void* d_out, int out_size)
{
    (void)in_sizes; (void)n_in; (void)out_size;
    const float* x       = (const float*)d_in[0];
    const float* theta_w = (const float*)d_in[1];
    const float* theta_b = (const float*)d_in[2];
    const float* phi_w   = (const float*)d_in[3];
    const float* phi_b   = (const float*)d_in[4];
    const float* g_w     = (const float*)d_in[5];
    const float* g_b     = (const float*)d_in[6];
    const float* w_w     = (const float*)d_in[7];
    const float* w_b     = (const float*)d_in[8];
    const float* gamma   = (const float*)d_in[9];
    const float* beta    = (const float*)d_in[10];
    float* out = (float*)d_out;

    float *p_theta, *p_phi, *p_g, *p_f, *p_y, *p_wy;
    cudaGetSymbolAddress((void**)&p_theta, s_theta);
    cudaGetSymbolAddress((void**)&p_phi,   s_phi);
    cudaGetSymbolAddress((void**)&p_g,     s_g);
    cudaGetSymbolAddress((void**)&p_f,     s_f);
    cudaGetSymbolAddress((void**)&p_y,     s_y);
    cudaGetSymbolAddress((void**)&p_wy,    s_wy);

    const dim3 blk(256);
    const long long sX  = (long long)CC * NN;   // x per-batch
    const long long sP  = (long long)CI * NN;   // projection per-batch
    const long long sF  = (long long)NN * NN;   // f per-batch
    const long long sWY = (long long)CC * NN;

    // 1) projections: [CI x C] @ [C x N] + bias  (NN gemm)
    const dim3 gproj((NN + 127) / 128, (CI + 127) / 128, BB);   // (25, 2, 8)
    sgemm_k<false, false, true><<<gproj, blk>>>(theta_w, x, theta_b, p_theta, CI, NN, CC, 0, sX, sP);
    sgemm_k<false, false, true><<<gproj, blk>>>(phi_w,   x, phi_b,   p_phi,   CI, NN, CC, 0, sX, sP);
    sgemm_k<false, false, true><<<gproj, blk>>>(g_w,     x, g_b,     p_g,     CI, NN, CC, 0, sX, sP);

    // 2) f[n][m] = sum_k theta[k][n]*phi[k][m]   (TN gemm, M=N=3136, K=256)
    const dim3 gf((NN + 127) / 128, (NN + 127) / 128, BB);      // (25, 25, 8)
    sgemm_k<true, false, false><<<gf, blk>>>(p_theta, p_phi, nullptr, p_f, NN, NN, CI, sP, sP, sF);

    // 3) row softmax over f
    softmax_kernel<<<BB * NN, blk>>>(p_f);

    // 4) y[ci][n] = sum_m g[ci][m] * P[n][m]    (NT gemm, M=256, N=3136, K=3136)
    const dim3 gy((NN + 127) / 128, (CI + 127) / 128, BB);      // (25, 2, 8)
    sgemm_k<false, true, false><<<gy, blk>>>(p_g, p_f, nullptr, p_y, CI, NN, NN, sP, sF, sP);

    // 5) w_y = w_w @ y + w_b                    (NN gemm, M=512, N=3136, K=256)
    const dim3 gw((NN + 127) / 128, (CC + 127) / 128, BB);      // (25, 4, 8)
    sgemm_k<false, false, true><<<gw, blk>>>(w_w, p_y, w_b, p_wy, CC, NN, CI, 0, sP, sWY);

    // 6) BN stats (deterministic) + 7) finalize with residual
    bnstats_kernel<<<CC, blk>>>(p_wy);
    bn_finalize_kernel<<<(unsigned)((size_t)BB * CC * NN / 4 / 256), blk>>>(p_wy, x, gamma, beta, out);
}

// round 10
// speedup vs baseline: 1.6203x; 1.6203x over previous
#include <cuda_runtime.h>
#include <cuda_bf16.h>
#include <cstdint>

#define BB 8
#define CC 512
#define CI 256
#define NN 3136
#define EPSBN 1e-5f

// ---- scratch (static device globals; no allocations allowed) ----
__device__ __align__(16) float s_theta[BB * CI * NN];
__device__ __align__(16) float s_phi  [BB * CI * NN];
__device__ __align__(16) float s_g    [BB * CI * NN];
__device__ __align__(16) float s_f    [BB * NN * NN];          // fp32 scores
__device__ __align__(16) float s_y    [BB * NN * CI];          // [n][ci] row-major
__device__ __align__(16) float s_wy   [BB * CC * NN];
__device__ float s_mean[CC];
__device__ float s_rstd[CC];

// split-bf16 operands
__device__ __align__(16) __nv_bfloat16 g_thT_hi[BB * NN * CI];
__device__ __align__(16) __nv_bfloat16 g_thT_lo[BB * NN * CI];
__device__ __align__(16) __nv_bfloat16 g_phT_hi[BB * NN * CI];
__device__ __align__(16) __nv_bfloat16 g_phT_lo[BB * NN * CI];
__device__ __align__(16) __nv_bfloat16 g_g_hi  [BB * CI * NN];
__device__ __align__(16) __nv_bfloat16 g_g_lo  [BB * CI * NN];
__device__ __align__(16) __nv_bfloat16 g_pf_hi [BB * (size_t)NN * NN];
__device__ __align__(16) __nv_bfloat16 g_pf_lo [BB * (size_t)NN * NN];

// ============================================================================
// Warp MMA helpers (sm_80+ ISA only — safe on base compute_103 target)
// ============================================================================
__device__ __forceinline__ uint32_t smem_u32(const void* p) {
    uint32_t a;
    asm("{ .reg .u64 t; cvta.to.shared.u64 t, %1; cvt.u32.u64 %0, t; }"
        : "=r"(a) : "l"(p));
    return a;
}
__device__ __forceinline__ void ldmx4(uint32_t* r, uint32_t addr) {
    asm volatile("ldmatrix.sync.aligned.m8n8.x4.shared.b16 {%0,%1,%2,%3}, [%4];"
                 : "=r"(r[0]), "=r"(r[1]), "=r"(r[2]), "=r"(r[3]) : "r"(addr));
}
__device__ __forceinline__ void mma16816(float* d, const uint32_t* a,
                                         uint32_t b0, uint32_t b1) {
    asm volatile("mma.sync.aligned.m16n8k16.row.col.f32.bf16.bf16.f32 "
                 "{%0,%1,%2,%3}, {%4,%5,%6,%7}, {%8,%9}, {%0,%1,%2,%3};"
                 : "+f"(d[0]), "+f"(d[1]), "+f"(d[2]), "+f"(d[3])
                 : "r"(a[0]), "r"(a[1]), "r"(a[2]), "r"(a[3]), "r"(b0), "r"(b1));
}
__device__ __forceinline__ void cp16(uint32_t saddr, const void* gaddr, uint32_t srcsz) {
    asm volatile("cp.async.cg.shared.global [%0], [%1], 16, %2;"
                 :: "r"(saddr), "l"(gaddr), "r"(srcsz) : "memory");
}

// ============================================================================
// HMMA split-bf16 GEMM: C[m][n] = sum_k A(m,k)*B(n,k), A [Mg x K], B [Ng x K]
// row-major bf16 hi/lo pairs, fp32 out. Block 128x128, Kc=64, 2-stage cp.async.
// ============================================================================
#define KC 64
#define TILE_B 16384                 // one 128x64 bf16 tile
#define STAGE_B 65536                // AH, AL, BH, BL
#define MMA_SMEM (2 * STAGE_B)       // 131072

// swizzled smem offset within a tile: rows of 128B, 16B chunk c ^ (row&7)
__device__ __forceinline__ uint32_t sw_off(int row, int chunk) {
    return (uint32_t)(row * 128 + ((chunk ^ (row & 7)) << 4));
}

__device__ __forceinline__ void stage_load(
    uint32_t st_base,   // shared addr of this stage
    const __nv_bfloat16* Ahi, const __nv_bfloat16* Alo,
    const __nv_bfloat16* Bhi, const __nv_bfloat16* Blo,
    int m0, int n0, int Mg, int Ng, int K, int k0, int tid)
{
    const int row = tid >> 1;
    const int cb = (tid & 1) * 4;
    // A tiles
    {
        const int gr = m0 + row;
        const uint32_t vsz = (gr < Mg) ? 16u : 0u;
        const int r = (gr < Mg) ? gr : 0;
        const __nv_bfloat16* sh = Ahi + (size_t)r * K + k0 + cb * 8;
        const __nv_bfloat16* sl = Alo + (size_t)r * K + k0 + cb * 8;
#pragma unroll
        for (int i = 0; i < 4; ++i) {
            uint32_t o = sw_off(row, cb + i);
            cp16(st_base + o,          sh + i * 8, vsz);
            cp16(st_base + TILE_B + o, sl + i * 8, vsz);
        }
    }
    // B tiles
    {
        const int gr = n0 + row;
        const uint32_t vsz = (gr < Ng) ? 16u : 0u;
        const int r = (gr < Ng) ? gr : 0;
        const __nv_bfloat16* sh = Bhi + (size_t)r * K + k0 + cb * 8;
        const __nv_bfloat16* sl = Blo + (size_t)r * K + k0 + cb * 8;
#pragma unroll
        for (int i = 0; i < 4; ++i) {
            uint32_t o = sw_off(row, cb + i);
            cp16(st_base + 2 * TILE_B + o, sh + i * 8, vsz);
            cp16(st_base + 3 * TILE_B + o, sl + i * 8, vsz);
        }
    }
}

__global__ void __launch_bounds__(256, 1) mma_gemm(
    const __nv_bfloat16* __restrict__ Ahi, const __nv_bfloat16* __restrict__ Alo,
    const __nv_bfloat16* __restrict__ Bhi, const __nv_bfloat16* __restrict__ Blo,
    float* __restrict__ C, int Mg, int Ng, int K,
    long long sA, long long sB, long long sC)
{
    extern __shared__ char smem[];
    const int tid = threadIdx.x;
    const int lane = tid & 31, wid = tid >> 5;
    const int m0 = blockIdx.y * 128, n0 = blockIdx.x * 128;
    Ahi += (size_t)blockIdx.z * sA;  Alo += (size_t)blockIdx.z * sA;
    Bhi += (size_t)blockIdx.z * sB;  Blo += (size_t)blockIdx.z * sB;
    C   += (size_t)blockIdx.z * sC;
    const uint32_t sb = smem_u32(smem);

    const int wm = (wid >> 1) * 32;      // warp m offset in block (0/32/64/96)
    const int wn = (wid & 1) * 64;       // warp n offset (0/64)
    const int gi = lane >> 3, rin = lane & 7;

    float acc[2][8][4];
#pragma unroll
    for (int a = 0; a < 2; ++a)
#pragma unroll
        for (int b = 0; b < 8; ++b)
#pragma unroll
            for (int c = 0; c < 4; ++c) acc[a][b][c] = 0.f;

    const int nkc = K / KC;
    // prologue: stage 0
    stage_load(sb, Ahi, Alo, Bhi, Blo, m0, n0, Mg, Ng, K, 0, tid);
    asm volatile("cp.async.commit_group;" ::: "memory");

    for (int cchunk = 0; cchunk < nkc; ++cchunk) {
        if (cchunk + 1 < nkc) {
            stage_load(sb + ((cchunk + 1) & 1) * STAGE_B, Ahi, Alo, Bhi, Blo,
                       m0, n0, Mg, Ng, K, (cchunk + 1) * KC, tid);
            asm volatile("cp.async.commit_group;" ::: "memory");
            asm volatile("cp.async.wait_group 1;" ::: "memory");
        } else {
            asm volatile("cp.async.wait_group 0;" ::: "memory");
        }
        __syncthreads();

        const uint32_t stB = sb + (cchunk & 1) * STAGE_B;
#pragma unroll
        for (int ks = 0; ks < 4; ++ks) {
            uint32_t Ah[2][4], Al[2][4];
#pragma unroll
            for (int mt = 0; mt < 2; ++mt) {
                const int rowA = wm + mt * 16 + (gi & 1) * 8 + rin;
                const int chA = ks * 2 + (gi >> 1);
                const uint32_t aaddr = stB + sw_off(rowA, chA);
                ldmx4(Ah[mt], aaddr);
                ldmx4(Al[mt], aaddr + TILE_B);
            }
#pragma unroll
            for (int np = 0; np < 4; ++np) {
                const int rowB = wn + np * 16 + (gi >> 1) * 8 + rin;
                const int chB = ks * 2 + (gi & 1);
                const uint32_t baddr = stB + 2 * TILE_B + sw_off(rowB, chB);
                uint32_t Bh[4], Bl[4];
                ldmx4(Bh, baddr);
                ldmx4(Bl, baddr + TILE_B);
#pragma unroll
                for (int mt = 0; mt < 2; ++mt) {
                    mma16816(acc[mt][np * 2],     Ah[mt], Bh[0], Bh[1]);
                    mma16816(acc[mt][np * 2],     Al[mt], Bh[0], Bh[1]);
                    mma16816(acc[mt][np * 2],     Ah[mt], Bl[0], Bl[1]);
                    mma16816(acc[mt][np * 2 + 1], Ah[mt], Bh[2], Bh[3]);
                    mma16816(acc[mt][np * 2 + 1], Al[mt], Bh[2], Bh[3]);
                    mma16816(acc[mt][np * 2 + 1], Ah[mt], Bl[2], Bl[3]);
                }
            }
        }
        __syncthreads();
    }

    // ---- epilogue: direct stores ----
    const int g = lane >> 2, tg = lane & 3;
#pragma unroll
    for (int mt = 0; mt < 2; ++mt) {
#pragma unroll
        for (int nt = 0; nt < 8; ++nt) {
            const int row0 = m0 + wm + mt * 16 + g;
            const int col = n0 + wn + nt * 8 + tg * 2;
            if (col < Ng) {
                if (row0 < Mg) {
                    float2 v; v.x = acc[mt][nt][0]; v.y = acc[mt][nt][1];
                    *(float2*)(C + (size_t)row0 * Ng + col) = v;
                }
                if (row0 + 8 < Mg) {
                    float2 v; v.x = acc[mt][nt][2]; v.y = acc[mt][nt][3];
                    *(float2*)(C + (size_t)(row0 + 8) * Ng + col) = v;
                }
            }
        }
    }
}

// ============================================================================
// Classic SGEMM (projections and W)
// ============================================================================
template <bool TA, bool TB, bool BIAS>
__global__ __launch_bounds__(256) void sgemm_k(
    const float* __restrict__ A, const float* __restrict__ B,
    const float* __restrict__ bias, float* __restrict__ C,
    int M, int N, int K,
    long long strideA, long long strideB, long long strideC)
{
    __shared__ float As[16][128];
    __shared__ float Bs[16][128];

    const int tid = threadIdx.x;
    const int m0 = blockIdx.y * 128;
    const int n0 = blockIdx.x * 128;
    A += (size_t)blockIdx.z * (size_t)strideA;
    B += (size_t)blockIdx.z * (size_t)strideB;
    C += (size_t)blockIdx.z * (size_t)strideC;

    const int ty = tid >> 4;
    const int tx = tid & 15;
    const int rowc = ty * 8;
    const int colc = tx * 8;

    float acc[8][8];
#pragma unroll
    for (int i = 0; i < 8; ++i)
#pragma unroll
        for (int j = 0; j < 8; ++j) acc[i][j] = 0.f;

    for (int k0 = 0; k0 < K; k0 += 16) {
        if (!TA) {
            const int ar = tid >> 2;
            const int ac = (tid & 3) << 2;
#pragma unroll
            for (int r = 0; r < 2; ++r) {
                int m = m0 + ar + r * 64;
                float4 v = make_float4(0.f, 0.f, 0.f, 0.f);
                if (m < M) v = *(const float4*)(A + (size_t)m * K + k0 + ac);
                As[ac + 0][ar + r * 64] = v.x;
                As[ac + 1][ar + r * 64] = v.y;
                As[ac + 2][ar + r * 64] = v.z;
                As[ac + 3][ar + r * 64] = v.w;
            }
        } else {
            const int ak = tid >> 5;
            const int am = (tid & 31) << 2;
#pragma unroll
            for (int r = 0; r < 2; ++r) {
                int k = k0 + ak + r * 8;
                int m = m0 + am;
                float4 v = make_float4(0.f, 0.f, 0.f, 0.f);
                if (m < M) v = *(const float4*)(A + (size_t)k * M + m);
                *(float4*)&As[ak + r * 8][am] = v;
            }
        }
        if (!TB) {
            const int bk = tid >> 5;
            const int bn = (tid & 31) << 2;
#pragma unroll
            for (int r = 0; r < 2; ++r) {
                int k = k0 + bk + r * 8;
                int n = n0 + bn;
                float4 v = make_float4(0.f, 0.f, 0.f, 0.f);
                if (n < N) v = *(const float4*)(B + (size_t)k * N + n);
                *(float4*)&Bs[bk + r * 8][bn] = v;
            }
        } else {
            const int br = tid >> 2;
            const int bc = (tid & 3) << 2;
#pragma unroll
            for (int r = 0; r < 2; ++r) {
                int n = n0 + br + r * 64;
                float4 v = make_float4(0.f, 0.f, 0.f, 0.f);
                if (n < N) v = *(const float4*)(B + (size_t)n * K + k0 + bc);
                Bs[bc + 0][br + r * 64] = v.x;
                Bs[bc + 1][br + r * 64] = v.y;
                Bs[bc + 2][br + r * 64] = v.z;
                Bs[bc + 3][br + r * 64] = v.w;
            }
        }
        __syncthreads();

#pragma unroll
        for (int k = 0; k < 16; ++k) {
            float ra[8], rb[8];
            *(float4*)&ra[0] = *(const float4*)&As[k][rowc];
            *(float4*)&ra[4] = *(const float4*)&As[k][rowc + 4];
            *(float4*)&rb[0] = *(const float4*)&Bs[k][colc];
            *(float4*)&rb[4] = *(const float4*)&Bs[k][colc + 4];
#pragma unroll
            for (int i = 0; i < 8; ++i)
#pragma unroll
                for (int j = 0; j < 8; ++j)
                    acc[i][j] = fmaf(ra[i], rb[j], acc[i][j]);
        }
        __syncthreads();
    }

#pragma unroll
    for (int i = 0; i < 8; ++i) {
        int m = m0 + rowc + i;
        if (m >= M) continue;
        float bv = 0.f;
        if (BIAS) bv = bias[m];
        float* crow = C + (size_t)m * N;
#pragma unroll
        for (int jj = 0; jj < 2; ++jj) {
            int n = n0 + colc + jj * 4;
            if (n < N) {
                float4 v;
                v.x = acc[i][jj * 4 + 0] + bv;
                v.y = acc[i][jj * 4 + 1] + bv;
                v.z = acc[i][jj * 4 + 2] + bv;
                v.w = acc[i][jj * 4 + 3] + bv;
                *(float4*)(crow + n) = v;
            }
        }
    }
}

// ============================================================================
// Conversions: fp32 -> split bf16 (hi + lo)
// ============================================================================
__device__ __forceinline__ void split_bf(float v, __nv_bfloat16& h, __nv_bfloat16& l) {
    h = __float2bfloat16(v);
    l = __float2bfloat16(v - __bfloat162float(h));
}

// in [B][CI][NN] fp32 -> out [B][NN][CI] bf16 (transpose + split)
__global__ __launch_bounds__(256) void split_T_kernel(
    const float* __restrict__ in,
    __nv_bfloat16* __restrict__ ohi, __nv_bfloat16* __restrict__ olo)
{
    __shared__ float t[32][33];
    const int b = blockIdx.z;
    const int n0 = blockIdx.x * 32, c0 = blockIdx.y * 32;
    const float* src = in + (size_t)b * CI * NN;
    const int tx = threadIdx.x & 31, ty = threadIdx.x >> 5;
#pragma unroll
    for (int r = 0; r < 4; ++r)
        t[ty + r * 8][tx] = src[(size_t)(c0 + ty + r * 8) * NN + n0 + tx];
    __syncthreads();
    __nv_bfloat16* dhi = ohi + (size_t)b * NN * CI;
    __nv_bfloat16* dlo = olo + (size_t)b * NN * CI;
#pragma unroll
    for (int r = 0; r < 4; ++r) {
        float v = t[tx][ty + r * 8];
        __nv_bfloat16 h, l; split_bf(v, h, l);
        size_t o = (size_t)(n0 + ty + r * 8) * CI + c0 + tx;
        dhi[o] = h; dlo[o] = l;
    }
}

// elementwise split (same layout)
__global__ __launch_bounds__(256) void split4_kernel(
    const float* __restrict__ in,
    __nv_bfloat16* __restrict__ ohi, __nv_bfloat16* __restrict__ olo, size_t n4)
{
    size_t i = (size_t)blockIdx.x * 256 + threadIdx.x;
    if (i >= n4) return;
    float4 v = ((const float4*)in)[i];
    __nv_bfloat16 h0, l0, h1, l1, h2, l2, h3, l3;
    split_bf(v.x, h0, l0); split_bf(v.y, h1, l1);
    split_bf(v.z, h2, l2); split_bf(v.w, h3, l3);
    __nv_bfloat162 hp0; hp0.x = h0; hp0.y = h1;
    __nv_bfloat162 hp1; hp1.x = h2; hp1.y = h3;
    __nv_bfloat162 lp0; lp0.x = l0; lp0.y = l1;
    __nv_bfloat162 lp1; lp1.x = l2; lp1.y = l3;
    ((__nv_bfloat162*)ohi)[i * 2]     = hp0;
    ((__nv_bfloat162*)ohi)[i * 2 + 1] = hp1;
    ((__nv_bfloat162*)olo)[i * 2]     = lp0;
    ((__nv_bfloat162*)olo)[i * 2 + 1] = lp1;
}

// ============================================================================
// Row softmax over f (fp32 in) -> split bf16 probabilities out
// ============================================================================
__global__ __launch_bounds__(256) void softmax_kernel(
    const float* __restrict__ f,
    __nv_bfloat16* __restrict__ pf_hi, __nv_bfloat16* __restrict__ pf_lo)
{
    __shared__ float4 buf[NN / 4];
    __shared__ float red[8];
    const float* row = f + (size_t)blockIdx.x * NN;
    __nv_bfloat16* rh = pf_hi + (size_t)blockIdx.x * NN;
    __nv_bfloat16* rl = pf_lo + (size_t)blockIdx.x * NN;
    const int tid = threadIdx.x;

    float mx = -1e30f;
    for (int i = tid; i < NN / 4; i += 256) {
        float4 v = *(const float4*)(row + i * 4);
        buf[i] = v;
        mx = fmaxf(mx, fmaxf(fmaxf(v.x, v.y), fmaxf(v.z, v.w)));
    }
#pragma unroll
    for (int o = 16; o > 0; o >>= 1) mx = fmaxf(mx, __shfl_xor_sync(0xffffffffu, mx, o));
    if ((tid & 31) == 0) red[tid >> 5] = mx;
    __syncthreads();
    if (tid == 0) {
        float v = red[0];
        for (int i = 1; i < 8; ++i) v = fmaxf(v, red[i]);
        red[0] = v;
    }
    __syncthreads();
    mx = red[0];
    __syncthreads();

    float sum = 0.f;
    for (int i = tid; i < NN / 4; i += 256) {
        float4 v = buf[i];
        v.x = __expf(v.x - mx); v.y = __expf(v.y - mx);
        v.z = __expf(v.z - mx); v.w = __expf(v.w - mx);
        buf[i] = v;
        sum += v.x + v.y + v.z + v.w;
    }
#pragma unroll
    for (int o = 16; o > 0; o >>= 1) sum += __shfl_xor_sync(0xffffffffu, sum, o);
    if ((tid & 31) == 0) red[tid >> 5] = sum;
    __syncthreads();
    if (tid == 0) {
        float v = 0.f;
        for (int i = 0; i < 8; ++i) v += red[i];
        red[0] = v;
    }
    __syncthreads();
    const float inv = 1.f / red[0];

    for (int i = tid; i < NN / 4; i += 256) {
        float4 v = buf[i];
        v.x *= inv; v.y *= inv; v.z *= inv; v.w *= inv;
        __nv_bfloat16 h0, l0, h1, l1, h2, l2, h3, l3;
        split_bf(v.x, h0, l0); split_bf(v.y, h1, l1);
        split_bf(v.z, h2, l2); split_bf(v.w, h3, l3);
        __nv_bfloat162 hp0; hp0.x = h0; hp0.y = h1;
        __nv_bfloat162 hp1; hp1.x = h2; hp1.y = h3;
        __nv_bfloat162 lp0; lp0.x = l0; lp0.y = l1;
        __nv_bfloat162 lp1; lp1.x = l2; lp1.y = l3;
        ((__nv_bfloat162*)rh)[i * 2]     = hp0;
        ((__nv_bfloat162*)rh)[i * 2 + 1] = hp1;
        ((__nv_bfloat162*)rl)[i * 2]     = lp0;
        ((__nv_bfloat162*)rl)[i * 2 + 1] = lp1;
    }
}

// ============================================================================
// BatchNorm stats + finalize
// ============================================================================
__global__ __launch_bounds__(256) void bnstats_kernel(const float* __restrict__ wy)
{
    const int c = blockIdx.x;
    const int tid = threadIdx.x;
    float s = 0.f, s2 = 0.f;
    for (int b = 0; b < BB; ++b) {
        const float* row = wy + ((size_t)b * CC + c) * NN;
        for (int i = tid; i < NN / 4; i += 256) {
            float4 v = *(const float4*)(row + i * 4);
            s  += v.x + v.y + v.z + v.w;
            s2 += v.x * v.x + v.y * v.y + v.z * v.z + v.w * v.w;
        }
    }
#pragma unroll
    for (int o = 16; o > 0; o >>= 1) {
        s  += __shfl_xor_sync(0xffffffffu, s, o);
        s2 += __shfl_xor_sync(0xffffffffu, s2, o);
    }
    __shared__ float rs[8], rs2[8];
    if ((tid & 31) == 0) { rs[tid >> 5] = s; rs2[tid >> 5] = s2; }
    __syncthreads();
    if (tid == 0) {
        float ts = 0.f, ts2 = 0.f;
        for (int i = 0; i < 8; ++i) { ts += rs[i]; ts2 += rs2[i]; }
        const float cnt = (float)(BB * NN);
        const float mean = ts / cnt;
        const float var = ts2 / cnt - mean * mean;
        s_mean[c] = mean;
        s_rstd[c] = rsqrtf(var + EPSBN);
    }
}

__global__ __launch_bounds__(256) void bn_finalize_kernel(
    const float* __restrict__ wy, const float* __restrict__ x,
    const float* __restrict__ gamma, const float* __restrict__ beta,
    float* __restrict__ out)
{
    const size_t i4 = (size_t)blockIdx.x * 256 + threadIdx.x;
    const size_t total4 = (size_t)BB * CC * NN / 4;
    if (i4 >= total4) return;
    const size_t i = i4 * 4;
    const int c = (int)((i / NN) % CC);
    float4 w  = *(const float4*)(wy + i);
    float4 xv = *(const float4*)(x + i);
    const float m = s_mean[c], r = s_rstd[c];
    const float gm = gamma[c], bt = beta[c];
    float4 o;
    o.x = (w.x - m) * r * gm + bt + xv.x;
    o.y = (w.y - m) * r * gm + bt + xv.y;
    o.z = (w.z - m) * r * gm + bt + xv.z;
    o.w = (w.w - m) * r * gm + bt + xv.w;
    *(float4*)(out + i) = o;
}

// ============================================================================
// Launch
// ============================================================================
extern "C" void kernel_launch(void* const* d_in, const int* in_sizes, int n_in,
                              void* d_out, int out_size)
{
    (void)in_sizes; (void)n_in; (void)out_size;
    const float* x       = (const float*)d_in[0];
    const float* theta_w = (const float*)d_in[1];
    const float* theta_b = (const float*)d_in[2];
    const float* phi_w   = (const float*)d_in[3];
    const float* phi_b   = (const float*)d_in[4];
    const float* g_w     = (const float*)d_in[5];
    const float* g_b     = (const float*)d_in[6];
    const float* w_w     = (const float*)d_in[7];
    const float* w_b     = (const float*)d_in[8];
    const float* gamma   = (const float*)d_in[9];
    const float* beta    = (const float*)d_in[10];
    float* out = (float*)d_out;

    float *p_theta, *p_phi, *p_g, *p_f, *p_y, *p_wy;
    __nv_bfloat16 *p_thT_hi, *p_thT_lo, *p_phT_hi, *p_phT_lo, *p_g_hi, *p_g_lo;
    __nv_bfloat16 *p_pf_hi, *p_pf_lo;
    cudaGetSymbolAddress((void**)&p_theta,  s_theta);
    cudaGetSymbolAddress((void**)&p_phi,    s_phi);
    cudaGetSymbolAddress((void**)&p_g,      s_g);
    cudaGetSymbolAddress((void**)&p_f,      s_f);
    cudaGetSymbolAddress((void**)&p_y,      s_y);
    cudaGetSymbolAddress((void**)&p_wy,     s_wy);
    cudaGetSymbolAddress((void**)&p_thT_hi, g_thT_hi);
    cudaGetSymbolAddress((void**)&p_thT_lo, g_thT_lo);
    cudaGetSymbolAddress((void**)&p_phT_hi, g_phT_hi);
    cudaGetSymbolAddress((void**)&p_phT_lo, g_phT_lo);
    cudaGetSymbolAddress((void**)&p_g_hi,   g_g_hi);
    cudaGetSymbolAddress((void**)&p_g_lo,   g_g_lo);
    cudaGetSymbolAddress((void**)&p_pf_hi,  g_pf_hi);
    cudaGetSymbolAddress((void**)&p_pf_lo,  g_pf_lo);

    cudaFuncSetAttribute(mma_gemm, cudaFuncAttributeMaxDynamicSharedMemorySize, MMA_SMEM);

    const dim3 blk(256);
    const long long sX  = (long long)CC * NN;
    const long long sP  = (long long)CI * NN;
    const long long sF  = (long long)NN * NN;
    const long long sWY = (long long)CC * NN;

    // 1) projections (fp32 SGEMM): [CI x C] @ [C x N] + bias
    const dim3 gproj((NN + 127) / 128, (CI + 127) / 128, BB);
    sgemm_k<false, false, true><<<gproj, blk>>>(theta_w, x, theta_b, p_theta, CI, NN, CC, 0, sX, sP);
    sgemm_k<false, false, true><<<gproj, blk>>>(phi_w,   x, phi_b,   p_phi,   CI, NN, CC, 0, sX, sP);
    sgemm_k<false, false, true><<<gproj, blk>>>(g_w,     x, g_b,     p_g,     CI, NN, CC, 0, sX, sP);

    // 2) convert to split-bf16 operand layouts
    const dim3 gsT(NN / 32, CI / 32, BB);
    split_T_kernel<<<gsT, blk>>>(p_theta, p_thT_hi, p_thT_lo);
    split_T_kernel<<<gsT, blk>>>(p_phi,   p_phT_hi, p_phT_lo);
    const size_t n4g = (size_t)BB * CI * NN / 4;
    split4_kernel<<<(unsigned)((n4g + 255) / 256), blk>>>(p_g, p_g_hi, p_g_lo, n4g);

    // 3) f[n][m] = sum_k thT[n][k] * phT[m][k]   (HMMA, M=3136, N=3136, K=256)
    const dim3 gf((NN + 127) / 128, (NN + 127) / 128, BB);   // (25, 25, 8)
    mma_gemm<<<gf, blk, MMA_SMEM>>>(p_thT_hi, p_thT_lo, p_phT_hi, p_phT_lo,
                                    p_f, NN, NN, CI,
                                    (long long)NN * CI, (long long)NN * CI, sF);

    // 4) softmax -> split-bf16 probabilities
    softmax_kernel<<<BB * NN, blk>>>(p_f, p_pf_hi, p_pf_lo);

    // 5) y[n][c] = sum_m Pf[n][m] * g[c][m]      (HMMA, M=3136, N=256, K=3136)
    const dim3 gy((CI + 127) / 128, (NN + 127) / 128, BB);   // (2, 25, 8)
    mma_gemm<<<gy, blk, MMA_SMEM>>>(p_pf_hi, p_pf_lo, p_g_hi, p_g_lo,
                                    p_y, NN, CI, NN,
                                    sF, (long long)CI * NN, (long long)NN * CI);

    // 6) w_y[o][n] = sum_c w_w[o][c] * y[n][c]   (SGEMM, TB: y is [NN x CI])
    const dim3 gw((NN + 127) / 128, (CC + 127) / 128, BB);
    sgemm_k<false, true, true><<<gw, blk>>>(w_w, p_y, w_b, p_wy, CC, NN, CI,
                                            0, (long long)NN * CI, sWY);

    // 7) BN stats + finalize with residual
    bnstats_kernel<<<CC, blk>>>(p_wy);
    bn_finalize_kernel<<<(unsigned)((size_t)BB * CC * NN / 4 / 256), blk>>>(p_wy, x, gamma, beta, out);
}

// round 12
// speedup vs baseline: 2.2565x; 1.3926x over previous
#include <cuda_runtime.h>
#include <cuda_bf16.h>
#include <cstdint>

#define BB 8
#define CC 512
#define CI 256
#define NN 3136
#define EPSBN 1e-5f

// ---- scratch (static device globals; no allocations allowed) ----
__device__ __align__(16) float s_f  [BB * NN * NN];            // fp32 scores
__device__ __align__(16) float s_wy [BB * CC * NN];
__device__ float s_mean[CC];
__device__ float s_rstd[CC];

// split-bf16 operands
__device__ __align__(16) __nv_bfloat16 g_xT_hi [BB * NN * CC]; // x^T [B][N][C]
__device__ __align__(16) __nv_bfloat16 g_xT_lo [BB * NN * CC];
__device__ __align__(16) __nv_bfloat16 g_thT_hi[BB * NN * CI];
__device__ __align__(16) __nv_bfloat16 g_thT_lo[BB * NN * CI];
__device__ __align__(16) __nv_bfloat16 g_phT_hi[BB * NN * CI];
__device__ __align__(16) __nv_bfloat16 g_phT_lo[BB * NN * CI];
__device__ __align__(16) __nv_bfloat16 g_g_hi  [BB * CI * NN];
__device__ __align__(16) __nv_bfloat16 g_g_lo  [BB * CI * NN];
__device__ __align__(16) __nv_bfloat16 g_y_hi  [BB * NN * CI]; // y [N][CI]
__device__ __align__(16) __nv_bfloat16 g_y_lo  [BB * NN * CI];
__device__ __align__(16) __nv_bfloat16 g_pf_hi [BB * (size_t)NN * NN];
__device__ __align__(16) __nv_bfloat16 g_pf_lo [BB * (size_t)NN * NN];
// weight splits
__device__ __align__(16) __nv_bfloat16 g_tw_hi[CI * CC], g_tw_lo[CI * CC];
__device__ __align__(16) __nv_bfloat16 g_pw_hi[CI * CC], g_pw_lo[CI * CC];
__device__ __align__(16) __nv_bfloat16 g_gw_hi[CI * CC], g_gw_lo[CI * CC];
__device__ __align__(16) __nv_bfloat16 g_ww_hi[CC * CI], g_ww_lo[CC * CI];

// ============================================================================
// Warp MMA helpers (sm_80+ ISA only — safe on base compute_103 target)
// ============================================================================
__device__ __forceinline__ uint32_t smem_u32(const void* p) {
    uint32_t a;
    asm("{ .reg .u64 t; cvta.to.shared.u64 t, %1; cvt.u32.u64 %0, t; }"
        : "=r"(a) : "l"(p));
    return a;
}
__device__ __forceinline__ void ldmx4(uint32_t* r, uint32_t addr) {
    asm volatile("ldmatrix.sync.aligned.m8n8.x4.shared.b16 {%0,%1,%2,%3}, [%4];"
                 : "=r"(r[0]), "=r"(r[1]), "=r"(r[2]), "=r"(r[3]) : "r"(addr));
}
__device__ __forceinline__ void mma16816(float* d, const uint32_t* a,
                                         uint32_t b0, uint32_t b1) {
    asm volatile("mma.sync.aligned.m16n8k16.row.col.f32.bf16.bf16.f32 "
                 "{%0,%1,%2,%3}, {%4,%5,%6,%7}, {%8,%9}, {%0,%1,%2,%3};"
                 : "+f"(d[0]), "+f"(d[1]), "+f"(d[2]), "+f"(d[3])
                 : "r"(a[0]), "r"(a[1]), "r"(a[2]), "r"(a[3]), "r"(b0), "r"(b1));
}
__device__ __forceinline__ void cp16(uint32_t saddr, const void* gaddr, uint32_t srcsz) {
    asm volatile("cp.async.cg.shared.global [%0], [%1], 16, %2;"
                 :: "r"(saddr), "l"(gaddr), "r"(srcsz) : "memory");
}
__device__ __forceinline__ void split_bf(float v, __nv_bfloat16& h, __nv_bfloat16& l) {
    h = __float2bfloat16(v);
    l = __float2bfloat16(v - __bfloat162float(h));
}

// ============================================================================
// HMMA split-bf16 GEMM: C[m][n] = sum_k A(m,k)*B(n,k), A [Mg x K], B [Ng x K]
// row-major bf16 hi/lo pairs. Block 128x128, Kc=64, 2-stage cp.async.
// OUTM: 0 = fp32 C;  1 = split bf16 (Chi, Clo)
// BIASM: 0 none; 1 bias[m] (row); 2 bias[n] (col)
// ============================================================================
#define KC 64
#define TILE_B 16384                 // one 128x64 bf16 tile
#define STAGE_B 65536                // AH, AL, BH, BL
#define MMA_SMEM (2 * STAGE_B)       // 131072

__device__ __forceinline__ uint32_t sw_off(int row, int chunk) {
    return (uint32_t)(row * 128 + ((chunk ^ (row & 7)) << 4));
}

__device__ __forceinline__ void stage_load(
    uint32_t st_base,
    const __nv_bfloat16* Ahi, const __nv_bfloat16* Alo,
    const __nv_bfloat16* Bhi, const __nv_bfloat16* Blo,
    int m0, int n0, int Mg, int Ng, int K, int k0, int tid)
{
    const int row = tid >> 1;
    const int cb = (tid & 1) * 4;
    {
        const int gr = m0 + row;
        const uint32_t vsz = (gr < Mg) ? 16u : 0u;
        const int r = (gr < Mg) ? gr : 0;
        const __nv_bfloat16* sh = Ahi + (size_t)r * K + k0 + cb * 8;
        const __nv_bfloat16* sl = Alo + (size_t)r * K + k0 + cb * 8;
#pragma unroll
        for (int i = 0; i < 4; ++i) {
            uint32_t o = sw_off(row, cb + i);
            cp16(st_base + o,          sh + i * 8, vsz);
            cp16(st_base + TILE_B + o, sl + i * 8, vsz);
        }
    }
    {
        const int gr = n0 + row;
        const uint32_t vsz = (gr < Ng) ? 16u : 0u;
        const int r = (gr < Ng) ? gr : 0;
        const __nv_bfloat16* sh = Bhi + (size_t)r * K + k0 + cb * 8;
        const __nv_bfloat16* sl = Blo + (size_t)r * K + k0 + cb * 8;
#pragma unroll
        for (int i = 0; i < 4; ++i) {
            uint32_t o = sw_off(row, cb + i);
            cp16(st_base + 2 * TILE_B + o, sh + i * 8, vsz);
            cp16(st_base + 3 * TILE_B + o, sl + i * 8, vsz);
        }
    }
}

template <int OUTM, int BIASM>
__global__ void __launch_bounds__(256, 1) mma_gemm(
    const __nv_bfloat16* __restrict__ Ahi, const __nv_bfloat16* __restrict__ Alo,
    const __nv_bfloat16* __restrict__ Bhi, const __nv_bfloat16* __restrict__ Blo,
    float* __restrict__ Cf,
    __nv_bfloat16* __restrict__ Chi, __nv_bfloat16* __restrict__ Clo,
    const float* __restrict__ bias,
    int Mg, int Ng, int K,
    long long sA, long long sB, long long sC)
{
    extern __shared__ char smem[];
    const int tid = threadIdx.x;
    const int lane = tid & 31, wid = tid >> 5;
    const int m0 = blockIdx.y * 128, n0 = blockIdx.x * 128;
    Ahi += (size_t)blockIdx.z * sA;  Alo += (size_t)blockIdx.z * sA;
    Bhi += (size_t)blockIdx.z * sB;  Blo += (size_t)blockIdx.z * sB;
    const uint32_t sb = smem_u32(smem);

    const int wm = (wid >> 1) * 32;
    const int wn = (wid & 1) * 64;
    const int gi = lane >> 3, rin = lane & 7;

    float acc[2][8][4];
#pragma unroll
    for (int a = 0; a < 2; ++a)
#pragma unroll
        for (int b = 0; b < 8; ++b)
#pragma unroll
            for (int c = 0; c < 4; ++c) acc[a][b][c] = 0.f;

    const int nkc = K / KC;
    stage_load(sb, Ahi, Alo, Bhi, Blo, m0, n0, Mg, Ng, K, 0, tid);
    asm volatile("cp.async.commit_group;" ::: "memory");

    for (int cchunk = 0; cchunk < nkc; ++cchunk) {
        if (cchunk + 1 < nkc) {
            stage_load(sb + ((cchunk + 1) & 1) * STAGE_B, Ahi, Alo, Bhi, Blo,
                       m0, n0, Mg, Ng, K, (cchunk + 1) * KC, tid);
            asm volatile("cp.async.commit_group;" ::: "memory");
            asm volatile("cp.async.wait_group 1;" ::: "memory");
        } else {
            asm volatile("cp.async.wait_group 0;" ::: "memory");
        }
        __syncthreads();

        const uint32_t stB = sb + (cchunk & 1) * STAGE_B;
#pragma unroll
        for (int ks = 0; ks < 4; ++ks) {
            uint32_t Ah[2][4], Al[2][4];
#pragma unroll
            for (int mt = 0; mt < 2; ++mt) {
                const int rowA = wm + mt * 16 + (gi & 1) * 8 + rin;
                const int chA = ks * 2 + (gi >> 1);
                const uint32_t aaddr = stB + sw_off(rowA, chA);
                ldmx4(Ah[mt], aaddr);
                ldmx4(Al[mt], aaddr + TILE_B);
            }
#pragma unroll
            for (int np = 0; np < 4; ++np) {
                const int rowB = wn + np * 16 + (gi >> 1) * 8 + rin;
                const int chB = ks * 2 + (gi & 1);
                const uint32_t baddr = stB + 2 * TILE_B + sw_off(rowB, chB);
                uint32_t Bh[4], Bl[4];
                ldmx4(Bh, baddr);
                ldmx4(Bl, baddr + TILE_B);
#pragma unroll
                for (int mt = 0; mt < 2; ++mt) {
                    mma16816(acc[mt][np * 2],     Ah[mt], Bh[0], Bh[1]);
                    mma16816(acc[mt][np * 2],     Al[mt], Bh[0], Bh[1]);
                    mma16816(acc[mt][np * 2],     Ah[mt], Bl[0], Bl[1]);
                    mma16816(acc[mt][np * 2 + 1], Ah[mt], Bh[2], Bh[3]);
                    mma16816(acc[mt][np * 2 + 1], Al[mt], Bh[2], Bh[3]);
                    mma16816(acc[mt][np * 2 + 1], Ah[mt], Bl[2], Bl[3]);
                }
            }
        }
        __syncthreads();
    }

    // ---- epilogue ----
    const int g = lane >> 2, tg = lane & 3;
#pragma unroll
    for (int mt = 0; mt < 2; ++mt) {
#pragma unroll
        for (int nt = 0; nt < 8; ++nt) {
            const int row0 = m0 + wm + mt * 16 + g;
            const int col = n0 + wn + nt * 8 + tg * 2;
            if (col >= Ng) continue;
            float bc0 = 0.f, bc1 = 0.f;
            if (BIASM == 2) { bc0 = bias[col]; bc1 = bias[col + 1]; }
#pragma unroll
            for (int h = 0; h < 2; ++h) {
                const int row = row0 + h * 8;
                if (row >= Mg) continue;
                float v0 = acc[mt][nt][h * 2], v1 = acc[mt][nt][h * 2 + 1];
                if (BIASM == 1) { float bv = bias[row]; v0 += bv; v1 += bv; }
                if (BIASM == 2) { v0 += bc0; v1 += bc1; }
                const size_t off = (size_t)blockIdx.z * sC + (size_t)row * Ng + col;
                if (OUTM == 0) {
                    float2 v; v.x = v0; v.y = v1;
                    *(float2*)(Cf + off) = v;
                } else {
                    __nv_bfloat16 h0, l0, h1, l1;
                    split_bf(v0, h0, l0); split_bf(v1, h1, l1);
                    __nv_bfloat162 hp; hp.x = h0; hp.y = h1;
                    __nv_bfloat162 lp; lp.x = l0; lp.y = l1;
                    *(__nv_bfloat162*)(Chi + off) = hp;
                    *(__nv_bfloat162*)(Clo + off) = lp;
                }
            }
        }
    }
}

// ============================================================================
// x: [B][CD][NN] fp32 -> [B][NN][CD] split bf16 (transpose + split), CD param
// ============================================================================
__global__ __launch_bounds__(256) void split_T_kernel(
    const float* __restrict__ in,
    __nv_bfloat16* __restrict__ ohi, __nv_bfloat16* __restrict__ olo, int CD)
{
    __shared__ float t[32][33];
    const int b = blockIdx.z;
    const int n0 = blockIdx.x * 32, c0 = blockIdx.y * 32;
    const float* src = in + (size_t)b * CD * NN;
    const int tx = threadIdx.x & 31, ty = threadIdx.x >> 5;
#pragma unroll
    for (int r = 0; r < 4; ++r)
        t[ty + r * 8][tx] = src[(size_t)(c0 + ty + r * 8) * NN + n0 + tx];
    __syncthreads();
    __nv_bfloat16* dhi = ohi + (size_t)b * NN * CD;
    __nv_bfloat16* dlo = olo + (size_t)b * NN * CD;
#pragma unroll
    for (int r = 0; r < 4; ++r) {
        float v = t[tx][ty + r * 8];
        __nv_bfloat16 h, l; split_bf(v, h, l);
        size_t o = (size_t)(n0 + ty + r * 8) * CD + c0 + tx;
        dhi[o] = h; dlo[o] = l;
    }
}

// elementwise split (weights)
__global__ __launch_bounds__(256) void split4_kernel(
    const float* __restrict__ in,
    __nv_bfloat16* __restrict__ ohi, __nv_bfloat16* __restrict__ olo, size_t n4)
{
    size_t i = (size_t)blockIdx.x * 256 + threadIdx.x;
    if (i >= n4) return;
    float4 v = ((const float4*)in)[i];
    __nv_bfloat16 h0, l0, h1, l1, h2, l2, h3, l3;
    split_bf(v.x, h0, l0); split_bf(v.y, h1, l1);
    split_bf(v.z, h2, l2); split_bf(v.w, h3, l3);
    __nv_bfloat162 hp0; hp0.x = h0; hp0.y = h1;
    __nv_bfloat162 hp1; hp1.x = h2; hp1.y = h3;
    __nv_bfloat162 lp0; lp0.x = l0; lp0.y = l1;
    __nv_bfloat162 lp1; lp1.x = l2; lp1.y = l3;
    ((__nv_bfloat162*)ohi)[i * 2]     = hp0;
    ((__nv_bfloat162*)ohi)[i * 2 + 1] = hp1;
    ((__nv_bfloat162*)olo)[i * 2]     = lp0;
    ((__nv_bfloat162*)olo)[i * 2 + 1] = lp1;
}

// ============================================================================
// Row softmax over f (fp32 in) -> split bf16 probabilities out
// ============================================================================
__global__ __launch_bounds__(256) void softmax_kernel(
    const float* __restrict__ f,
    __nv_bfloat16* __restrict__ pf_hi, __nv_bfloat16* __restrict__ pf_lo)
{
    __shared__ float4 buf[NN / 4];
    __shared__ float red[8];
    const float* row = f + (size_t)blockIdx.x * NN;
    __nv_bfloat16* rh = pf_hi + (size_t)blockIdx.x * NN;
    __nv_bfloat16* rl = pf_lo + (size_t)blockIdx.x * NN;
    const int tid = threadIdx.x;

    float mx = -1e30f;
    for (int i = tid; i < NN / 4; i += 256) {
        float4 v = *(const float4*)(row + i * 4);
        buf[i] = v;
        mx = fmaxf(mx, fmaxf(fmaxf(v.x, v.y), fmaxf(v.z, v.w)));
    }
#pragma unroll
    for (int o = 16; o > 0; o >>= 1) mx = fmaxf(mx, __shfl_xor_sync(0xffffffffu, mx, o));
    if ((tid & 31) == 0) red[tid >> 5] = mx;
    __syncthreads();
    if (tid == 0) {
        float v = red[0];
        for (int i = 1; i < 8; ++i) v = fmaxf(v, red[i]);
        red[0] = v;
    }
    __syncthreads();
    mx = red[0];
    __syncthreads();

    float sum = 0.f;
    for (int i = tid; i < NN / 4; i += 256) {
        float4 v = buf[i];
        v.x = __expf(v.x - mx); v.y = __expf(v.y - mx);
        v.z = __expf(v.z - mx); v.w = __expf(v.w - mx);
        buf[i] = v;
        sum += v.x + v.y + v.z + v.w;
    }
#pragma unroll
    for (int o = 16; o > 0; o >>= 1) sum += __shfl_xor_sync(0xffffffffu, sum, o);
    if ((tid & 31) == 0) red[tid >> 5] = sum;
    __syncthreads();
    if (tid == 0) {
        float v = 0.f;
        for (int i = 0; i < 8; ++i) v += red[i];
        red[0] = v;
    }
    __syncthreads();
    const float inv = 1.f / red[0];

    for (int i = tid; i < NN / 4; i += 256) {
        float4 v = buf[i];
        v.x *= inv; v.y *= inv; v.z *= inv; v.w *= inv;
        __nv_bfloat16 h0, l0, h1, l1, h2, l2, h3, l3;
        split_bf(v.x, h0, l0); split_bf(v.y, h1, l1);
        split_bf(v.z, h2, l2); split_bf(v.w, h3, l3);
        __nv_bfloat162 hp0; hp0.x = h0; hp0.y = h1;
        __nv_bfloat162 hp1; hp1.x = h2; hp1.y = h3;
        __nv_bfloat162 lp0; lp0.x = l0; lp0.y = l1;
        __nv_bfloat162 lp1; lp1.x = l2; lp1.y = l3;
        ((__nv_bfloat162*)rh)[i * 2]     = hp0;
        ((__nv_bfloat162*)rh)[i * 2 + 1] = hp1;
        ((__nv_bfloat162*)rl)[i * 2]     = lp0;
        ((__nv_bfloat162*)rl)[i * 2 + 1] = lp1;
    }
}

// ============================================================================
// BatchNorm stats + finalize
// ============================================================================
__global__ __launch_bounds__(256) void bnstats_kernel(const float* __restrict__ wy)
{
    const int c = blockIdx.x;
    const int tid = threadIdx.x;
    float s = 0.f, s2 = 0.f;
    for (int b = 0; b < BB; ++b) {
        const float* row = wy + ((size_t)b * CC + c) * NN;
        for (int i = tid; i < NN / 4; i += 256) {
            float4 v = *(const float4*)(row + i * 4);
            s  += v.x + v.y + v.z + v.w;
            s2 += v.x * v.x + v.y * v.y + v.z * v.z + v.w * v.w;
        }
    }
#pragma unroll
    for (int o = 16; o > 0; o >>= 1) {
        s  += __shfl_xor_sync(0xffffffffu, s, o);
        s2 += __shfl_xor_sync(0xffffffffu, s2, o);
    }
    __shared__ float rs[8], rs2[8];
    if ((tid & 31) == 0) { rs[tid >> 5] = s; rs2[tid >> 5] = s2; }
    __syncthreads();
    if (tid == 0) {
        float ts = 0.f, ts2 = 0.f;
        for (int i = 0; i < 8; ++i) { ts += rs[i]; ts2 += rs2[i]; }
        const float cnt = (float)(BB * NN);
        const float mean = ts / cnt;
        const float var = ts2 / cnt - mean * mean;
        s_mean[c] = mean;
        s_rstd[c] = rsqrtf(var + EPSBN);
    }
}

__global__ __launch_bounds__(256) void bn_finalize_kernel(
    const float* __restrict__ wy, const float* __restrict__ x,
    const float* __restrict__ gamma, const float* __restrict__ beta,
    float* __restrict__ out)
{
    const size_t i4 = (size_t)blockIdx.x * 256 + threadIdx.x;
    const size_t total4 = (size_t)BB * CC * NN / 4;
    if (i4 >= total4) return;
    const size_t i = i4 * 4;
    const int c = (int)((i / NN) % CC);
    float4 w  = *(const float4*)(wy + i);
    float4 xv = *(const float4*)(x + i);
    const float m = s_mean[c], r = s_rstd[c];
    const float gm = gamma[c], bt = beta[c];
    float4 o;
    o.x = (w.x - m) * r * gm + bt + xv.x;
    o.y = (w.y - m) * r * gm + bt + xv.y;
    o.z = (w.z - m) * r * gm + bt + xv.z;
    o.w = (w.w - m) * r * gm + bt + xv.w;
    *(float4*)(out + i) = o;
}

// ============================================================================
// Launch
// ============================================================================
extern "C" void kernel_launch(void* const* d_in, const int* in_sizes, int n_in,
                              void* d_out, int out_size)
{
    (void)in_sizes; (void)n_in; (void)out_size;
    const float* x       = (const float*)d_in[0];
    const float* theta_w = (const float*)d_in[1];
    const float* theta_b = (const float*)d_in[2];
    const float* phi_w   = (const float*)d_in[3];
    const float* phi_b   = (const float*)d_in[4];
    const float* g_w     = (const float*)d_in[5];
    const float* g_b     = (const float*)d_in[6];
    const float* w_w     = (const float*)d_in[7];
    const float* w_b     = (const float*)d_in[8];
    const float* gamma   = (const float*)d_in[9];
    const float* beta    = (const float*)d_in[10];
    float* out = (float*)d_out;

    float *p_f, *p_wy;
    __nv_bfloat16 *p_xT_hi, *p_xT_lo, *p_thT_hi, *p_thT_lo, *p_phT_hi, *p_phT_lo;
    __nv_bfloat16 *p_g_hi, *p_g_lo, *p_y_hi, *p_y_lo, *p_pf_hi, *p_pf_lo;
    __nv_bfloat16 *p_tw_hi, *p_tw_lo, *p_pw_hi, *p_pw_lo, *p_gw_hi, *p_gw_lo, *p_ww_hi, *p_ww_lo;
    cudaGetSymbolAddress((void**)&p_f,      s_f);
    cudaGetSymbolAddress((void**)&p_wy,     s_wy);
    cudaGetSymbolAddress((void**)&p_xT_hi,  g_xT_hi);
    cudaGetSymbolAddress((void**)&p_xT_lo,  g_xT_lo);
    cudaGetSymbolAddress((void**)&p_thT_hi, g_thT_hi);
    cudaGetSymbolAddress((void**)&p_thT_lo, g_thT_lo);
    cudaGetSymbolAddress((void**)&p_phT_hi, g_phT_hi);
    cudaGetSymbolAddress((void**)&p_phT_lo, g_phT_lo);
    cudaGetSymbolAddress((void**)&p_g_hi,   g_g_hi);
    cudaGetSymbolAddress((void**)&p_g_lo,   g_g_lo);
    cudaGetSymbolAddress((void**)&p_y_hi,   g_y_hi);
    cudaGetSymbolAddress((void**)&p_y_lo,   g_y_lo);
    cudaGetSymbolAddress((void**)&p_pf_hi,  g_pf_hi);
    cudaGetSymbolAddress((void**)&p_pf_lo,  g_pf_lo);
    cudaGetSymbolAddress((void**)&p_tw_hi,  g_tw_hi);
    cudaGetSymbolAddress((void**)&p_tw_lo,  g_tw_lo);
    cudaGetSymbolAddress((void**)&p_pw_hi,  g_pw_hi);
    cudaGetSymbolAddress((void**)&p_pw_lo,  g_pw_lo);
    cudaGetSymbolAddress((void**)&p_gw_hi,  g_gw_hi);
    cudaGetSymbolAddress((void**)&p_gw_lo,  g_gw_lo);
    cudaGetSymbolAddress((void**)&p_ww_hi,  g_ww_hi);
    cudaGetSymbolAddress((void**)&p_ww_lo,  g_ww_lo);

    cudaFuncSetAttribute(mma_gemm<0, 0>, cudaFuncAttributeMaxDynamicSharedMemorySize, MMA_SMEM);
    cudaFuncSetAttribute(mma_gemm<0, 1>, cudaFuncAttributeMaxDynamicSharedMemorySize, MMA_SMEM);
    cudaFuncSetAttribute(mma_gemm<1, 0>, cudaFuncAttributeMaxDynamicSharedMemorySize, MMA_SMEM);
    cudaFuncSetAttribute(mma_gemm<1, 1>, cudaFuncAttributeMaxDynamicSharedMemorySize, MMA_SMEM);
    cudaFuncSetAttribute(mma_gemm<1, 2>, cudaFuncAttributeMaxDynamicSharedMemorySize, MMA_SMEM);

    const dim3 blk(256);
    const long long sXT = (long long)NN * CC;
    const long long sP  = (long long)CI * NN;   // == NN*CI
    const long long sF  = (long long)NN * NN;

    // 0) operand conversions
    const dim3 gxT(NN / 32, CC / 32, BB);       // (98, 16, 8)
    split_T_kernel<<<gxT, blk>>>(x, p_xT_hi, p_xT_lo, CC);
    const size_t nw4 = (size_t)CI * CC / 4;
    split4_kernel<<<(unsigned)((nw4 + 255) / 256), blk>>>(theta_w, p_tw_hi, p_tw_lo, nw4);
    split4_kernel<<<(unsigned)((nw4 + 255) / 256), blk>>>(phi_w,   p_pw_hi, p_pw_lo, nw4);
    split4_kernel<<<(unsigned)((nw4 + 255) / 256), blk>>>(g_w,     p_gw_hi, p_gw_lo, nw4);
    split4_kernel<<<(unsigned)((nw4 + 255) / 256), blk>>>(w_w,     p_ww_hi, p_ww_lo, nw4);

    // 1) projections (HMMA, split-bf16 out, bias fused)
    //    theta/phi: [NN][CI] = xT @ w^T   (col bias)
    const dim3 gth(CI / 128, (NN + 127) / 128, BB);   // (2, 25, 8)
    mma_gemm<1, 2><<<gth, blk, MMA_SMEM>>>(p_xT_hi, p_xT_lo, p_tw_hi, p_tw_lo,
        nullptr, p_thT_hi, p_thT_lo, theta_b, NN, CI, CC, sXT, 0, sP);
    mma_gemm<1, 2><<<gth, blk, MMA_SMEM>>>(p_xT_hi, p_xT_lo, p_pw_hi, p_pw_lo,
        nullptr, p_phT_hi, p_phT_lo, phi_b, NN, CI, CC, sXT, 0, sP);
    //    g: [CI][NN] = g_w @ x   (row bias)
    const dim3 gg((NN + 127) / 128, CI / 128, BB);    // (25, 2, 8)
    mma_gemm<1, 1><<<gg, blk, MMA_SMEM>>>(p_gw_hi, p_gw_lo, p_xT_hi, p_xT_lo,
        nullptr, p_g_hi, p_g_lo, g_b, CI, NN, CC, 0, sXT, sP);

    // 2) f[n][m] = thT[n] . phT[m]   (HMMA, fp32 out)
    const dim3 gf((NN + 127) / 128, (NN + 127) / 128, BB);   // (25, 25, 8)
    mma_gemm<0, 0><<<gf, blk, MMA_SMEM>>>(p_thT_hi, p_thT_lo, p_phT_hi, p_phT_lo,
        p_f, nullptr, nullptr, nullptr, NN, NN, CI, sP, sP, sF);

    // 3) softmax -> split-bf16 probabilities
    softmax_kernel<<<BB * NN, blk>>>(p_f, p_pf_hi, p_pf_lo);

    // 4) y[n][c] = Pf[n] . g[c]      (HMMA, split-bf16 out)
    const dim3 gy(CI / 128, (NN + 127) / 128, BB);    // (2, 25, 8)
    mma_gemm<1, 0><<<gy, blk, MMA_SMEM>>>(p_pf_hi, p_pf_lo, p_g_hi, p_g_lo,
        nullptr, p_y_hi, p_y_lo, nullptr, NN, CI, NN, sF, sP, sP);

    // 5) wy[o][n] = w_w[o] . y[n]    (HMMA, fp32 out, row bias)
    const dim3 gw((NN + 127) / 128, CC / 128, BB);    // (25, 4, 8)
    mma_gemm<0, 1><<<gw, blk, MMA_SMEM>>>(p_ww_hi, p_ww_lo, p_y_hi, p_y_lo,
        p_wy, nullptr, nullptr, w_b, CC, NN, CI, 0, sP, (long long)CC * NN);

    // 6) BN stats + finalize with residual
    bnstats_kernel<<<CC, blk>>>(p_wy);
    bn_finalize_kernel<<<(unsigned)((size_t)BB * CC * NN / 4 / 256), blk>>>(p_wy, x, gamma, beta, out);
}